// round 10
// baseline (speedup 1.0000x reference)
#include <cuda_runtime.h>

#define NW   10
#define QDIM 1024
#define NBLK 4
#define WPB  4                    // warps (batch elements) per CTA
#define NTHREADS (WPB * 32)

// Precomputed phase tables (params-only, batch-independent).
// B[k][s]  = exp(-i/2 * (p3.z[s] + p2.z[perm[s]]))       (applied with gather by perm)
// C'[k][s] = exp(-i/2 * (p5.z[perm[s]] + pA(k+1).z[s]))  (C of block k folded with A of block k+1)
// A[0] is a global phase on |0..0> -> dropped.
__device__ float2 gB[NBLK][QDIM];
__device__ float2 gC[NBLK][QDIM];
__device__ float2 gRy[NBLK][2][NW];   // (cos(th/2), sin(th/2))

// CX-ring permutation, closed form (GF(2)-linear):
// out_i = b_i ^ b_{i+1} (i=0..7), out8 = b8^b9^b0, out9 = b9^b0
__host__ __device__ __forceinline__ int perm_of(int s) {
    int lo = (s ^ (s >> 1)) & 0xFF;
    int b0 = s & 1, b8 = (s >> 8) & 1, b9 = (s >> 9) & 1;
    return lo | ((b8 ^ b9 ^ b0) << 8) | ((b9 ^ b0) << 9);
}

__device__ __forceinline__ float dotz(const float* __restrict__ p, int s) {
    float d = 0.f;
    #pragma unroll
    for (int w = 0; w < NW; ++w)
        d += ((s >> (9 - w)) & 1) ? -p[w] : p[w];
    return d;
}

__global__ __launch_bounds__(QDIM)
void precompute_kernel(const float* __restrict__ params) {
    int s = threadIdx.x;                          // 0..1023
    if (s < NBLK * 2 * NW) {                      // RY coefficient table
        int k = s / (2 * NW), r = s % (2 * NW);
        int sweep = r / NW, w = r % NW;
        float th = params[(k * 6 + (sweep ? 4 : 1)) * NW + w];
        gRy[k][sweep][w] = make_float2(cosf(0.5f * th), sinf(0.5f * th));
    }
    int ps = perm_of(s);
    #pragma unroll 1
    for (int k = 0; k < NBLK; ++k) {
        const float* p = params + k * 6 * NW;
        float aB = dotz(p + 3 * NW, s) + dotz(p + 2 * NW, ps);
        float aC = dotz(p + 5 * NW, ps);
        if (k < NBLK - 1)                         // fold A of block k+1 into C of block k
            aC += dotz(params + ((k + 1) * 6 + 0) * NW, s);
        float c, si;
        sincosf(-0.5f * aB, &si, &c); gB[k][s] = make_float2(c, si);
        sincosf(-0.5f * aC, &si, &c); gC[k][s] = make_float2(c, si);
    }
}

__device__ __forceinline__ float2 cmul(float2 a, float2 b) {
    return make_float2(a.x * b.x - a.y * b.y, a.x * b.y + a.y * b.x);
}
// RY 2x2 on a register pair: u' = c*u - s*v ; v' = s*u + c*v
__device__ __forceinline__ void rotp(float2& u, float2& v, float c, float s) {
    float2 nu = make_float2(fmaf(c, u.x, -s * v.x), fmaf(c, u.y, -s * v.y));
    float2 nv = make_float2(fmaf(s, u.x,  c * v.x), fmaf(s, u.y,  c * v.y));
    u = nu; v = nv;
}

// Layouts:
//   L0: amplitude s = (h<<5)|lane   (reg h = bits 9..5, lane = bits 4..0)
//   L1: amplitude s = (lane<<5)|h   (lane = bits 9..5, reg h = bits 4..0)
// Shared swizzle: phys(s) = s ^ ((s>>5)&31)  -> conflict-free for all 4 patterns.
__global__ __launch_bounds__(NTHREADS)
void qsim_kernel(const float* __restrict__ x, float* __restrict__ out) {
    __shared__ float2 stage[WPB][QDIM];

    const int lane = threadIdx.x & 31;
    const int wid  = threadIdx.x >> 5;
    const int b    = blockIdx.x * WPB + wid;
    float2* st = stage[wid];

    float xv[NW];
    #pragma unroll
    for (int w = 0; w < NW; ++w) xv[w] = __ldg(&x[b * NW + w]);

    // Per-thread gather constant: addr = D[h] ^ pladj
    const int pl    = perm_of(lane);
    const int pladj = pl ^ ((lane & 1) ? 0x18 : 0);

    // Encoding angle contribution from lane bits (wires 5..9)
    float langle = 0.f;
    #pragma unroll
    for (int w = 5; w < NW; ++w)
        langle += ((lane >> (9 - w)) & 1) ? -xv[w] : xv[w];

    // |0...0> initial state (s=0 -> lane 0, reg 0); A[0] is a global phase (dropped)
    float2 r[32];
    #pragma unroll
    for (int h = 0; h < 32; ++h) r[h] = make_float2(0.f, 0.f);
    if (lane == 0) r[0].x = 1.f;

    // FULL unroll on k is load-bearing: it lets ptxas hoist/CSE every shared
    // address across the kernel (alu-pipe collapse, R8-verified). The global
    // table loops below stay at unroll 8 to bound MLP_p1 (R2-verified).
    #pragma unroll
    for (int k = 0; k < NBLK; ++k) {
        #pragma unroll
        for (int sweep = 0; sweep < 2; ++sweep) {
            // L0 in-register wires: w = 0..4, reg-bit rb = 4-w
            #pragma unroll
            for (int rb = 0; rb < 5; ++rb) {
                float2 rc = gRy[k][sweep][4 - rb];
                #pragma unroll
                for (int h = 0; h < 32; ++h)
                    if (!(h & (1 << rb)))
                        rotp(r[h], r[h | (1 << rb)], rc.x, rc.y);
            }
            // transpose L0 -> L1 through private warp stage
            __syncwarp();
            #pragma unroll
            for (int h = 0; h < 32; ++h)
                st[(h << 5) | (lane ^ h)] = r[h];
            __syncwarp();
            #pragma unroll
            for (int h = 0; h < 32; ++h)
                r[h] = st[(lane << 5) | (h ^ lane)];
            // L1 in-register wires: w = 5..9, reg-bit rb = 9-w
            #pragma unroll
            for (int rb = 0; rb < 5; ++rb) {
                float2 rc = gRy[k][sweep][9 - rb];
                #pragma unroll
                for (int h = 0; h < 32; ++h)
                    if (!(h & (1 << rb)))
                        rotp(r[h], r[h | (1 << rb)], rc.x, rc.y);
            }
            // write (L1) -> gather by perm into L0, fused diag B (sweep0) / C' (sweep1)
            __syncwarp();
            #pragma unroll
            for (int h = 0; h < 32; ++h)
                st[(lane << 5) | (h ^ lane)] = r[h];
            __syncwarp();
            const float2* __restrict__ T = (sweep == 0) ? gB[k] : gC[k];
            #pragma unroll 8
            for (int h = 0; h < 32; ++h) {
                const int C = perm_of(h << 5);            // compile-time
                const int D = C ^ ((C >> 5) & 31);        // compile-time
                float2 v = st[D ^ pladj];
                r[h] = cmul(v, __ldg(&T[(h << 5) | lane]));
            }
        }

        // --- batch encoding phase (k < last), state in L0 ---
        if (k != NBLK - 1) {
            #pragma unroll 8
            for (int h = 0; h < 32; ++h) {
                float ang = langle;
                #pragma unroll
                for (int w = 0; w < 5; ++w)
                    ang += ((h >> (4 - w)) & 1) ? -xv[w] : xv[w];
                float c, si;
                __sincosf(-0.5f * ang, &si, &c);
                r[h] = cmul(r[h], make_float2(c, si));
            }
        }
    }

    // --- expectation values: out[b][w] = sum_s |a_s|^2 * z[w][s] ---
    float acc[NW];
    #pragma unroll
    for (int w = 0; w < NW; ++w) acc[w] = 0.f;
    float totP = 0.f;
    #pragma unroll
    for (int h = 0; h < 32; ++h) {
        float p = fmaf(r[h].x, r[h].x, r[h].y * r[h].y);
        totP += p;
        #pragma unroll
        for (int w = 0; w < 5; ++w)                     // wires 0..4 <- reg bits
            acc[w] += ((h >> (4 - w)) & 1) ? -p : p;
    }
    #pragma unroll
    for (int w = 5; w < NW; ++w)                        // wires 5..9 <- lane bits
        acc[w] = ((lane >> (9 - w)) & 1) ? -totP : totP;

    #pragma unroll
    for (int off = 16; off; off >>= 1)
        #pragma unroll
        for (int w = 0; w < NW; ++w)
            acc[w] += __shfl_xor_sync(0xffffffffu, acc[w], off);

    if (lane == 0) {
        #pragma unroll
        for (int w = 0; w < NW; ++w) out[b * NW + w] = acc[w];
    }
}

extern "C" void kernel_launch(void* const* d_in, const int* in_sizes, int n_in,
                              void* d_out, int out_size) {
    const float* x      = (const float*)d_in[0];
    const float* params = (const float*)d_in[1];
    float* out = (float*)d_out;
    int bsz = in_sizes[0] / NW;           // 2048
    precompute_kernel<<<1, QDIM>>>(params);
    qsim_kernel<<<bsz / WPB, NTHREADS>>>(x, out);
}

// round 11
// speedup vs baseline: 2.8672x; 2.8672x over previous
#include <cuda_runtime.h>

#define NW    10
#define QDIM  1024
#define NBLK  4
#define NREG  16                    // amplitudes per thread
#define CTA   64                    // 2 warps = one batch element

// Phase tables (params-only). A folded into previous C'; A[0] = global phase (dropped).
// B[k][s]  = exp(-i/2 * (p3.z[s] + p2.z[perm[s]]))
// C'[k][s] = exp(-i/2 * (p5.z[perm[s]] + pA(k+1).z[s]))
__device__ float2 gB[NBLK][QDIM];
__device__ float2 gC[NBLK][QDIM];
__device__ float2 gRy[NBLK][2][NW];   // (cos(th/2), sin(th/2))

// CX-ring permutation, closed form (GF(2)-linear).
__host__ __device__ __forceinline__ int perm_of(int s) {
    int lo = (s ^ (s >> 1)) & 0xFF;
    int b0 = s & 1, b8 = (s >> 8) & 1, b9 = (s >> 9) & 1;
    return lo | ((b8 ^ b9 ^ b0) << 8) | ((b9 ^ b0) << 9);
}

__device__ __forceinline__ float dotz(const float* __restrict__ p, int s) {
    float d = 0.f;
    #pragma unroll
    for (int w = 0; w < NW; ++w)
        d += ((s >> (9 - w)) & 1) ? -p[w] : p[w];
    return d;
}

__global__ __launch_bounds__(QDIM)
void precompute_kernel(const float* __restrict__ params) {
    int s = threadIdx.x;
    if (s < NBLK * 2 * NW) {
        int k = s / (2 * NW), r = s % (2 * NW);
        int sweep = r / NW, w = r % NW;
        float th = params[(k * 6 + (sweep ? 4 : 1)) * NW + w];
        gRy[k][sweep][w] = make_float2(cosf(0.5f * th), sinf(0.5f * th));
    }
    int ps = perm_of(s);
    #pragma unroll 1
    for (int k = 0; k < NBLK; ++k) {
        const float* p = params + k * 6 * NW;
        float aB = dotz(p + 3 * NW, s) + dotz(p + 2 * NW, ps);
        float aC = dotz(p + 5 * NW, ps);
        if (k < NBLK - 1)
            aC += dotz(params + ((k + 1) * 6 + 0) * NW, s);
        float c, si;
        sincosf(-0.5f * aB, &si, &c); gB[k][s] = make_float2(c, si);
        sincosf(-0.5f * aC, &si, &c); gC[k][s] = make_float2(c, si);
    }
}

__device__ __forceinline__ float2 cmul(float2 a, float2 b) {
    return make_float2(a.x * b.x - a.y * b.y, a.x * b.y + a.y * b.x);
}
__device__ __forceinline__ void rotp(float2& u, float2& v, float c, float s) {
    float2 nu = make_float2(fmaf(c, u.x, -s * v.x), fmaf(c, u.y, -s * v.y));
    float2 nv = make_float2(fmaf(s, u.x,  c * v.x), fmaf(s, u.y,  c * v.y));
    u = nu; v = nv;
}

// Padded-affine shared layout (float2 units): loc(s) = (s>>5)*33 + (s&31).
// All transpose addresses are base_thread + compile-time offset -> immediate LDS/STS.
//
// Layout M0 (canonical): s = (h<<6) | (wbit<<5) | lane
//   h bits -> wires 0..3 ; wbit -> wire 4 ; lane bits -> wires 5..9
// Layout M1: s = wbit<<9 | l4<<8 | l3<<7 | l2<<6 | (h<<2) | l1<<1 | l0
//   h bits -> wires 4..7 ; lane bits l1,l0 -> wires 8,9 (shfl) ;
//   wbit/l4/l3/l2 -> wires 0..3 (covered by M0)
__global__ __launch_bounds__(CTA)
void qsim_kernel(const float* __restrict__ x, float* __restrict__ out) {
    __shared__ float2 st[32 * 33];
    __shared__ float  red[2][NW];

    const int tid  = threadIdx.x;
    const int lane = tid & 31;
    const int wbit = tid >> 5;
    const int b    = blockIdx.x;
    const int tb   = (wbit << 5) | lane;          // low 6 bits of M0 state

    float xv[NW];
    #pragma unroll
    for (int w = 0; w < NW; ++w) xv[w] = __ldg(&x[b * NW + w]);

    // gather per-thread constants: g = Kh ^ Pt (GF2-linear perm)
    const int Pt   = perm_of(tb);
    const int Pthi = Pt >> 5, Ptlo = Pt & 31;

    // encoding angle part from thread bits (wires 4..9 <-> tb bits 5..0)
    float langle = 0.f;
    #pragma unroll
    for (int w = 4; w < NW; ++w)
        langle += ((tb >> (9 - w)) & 1) ? -xv[w] : xv[w];

    // transpose address bases (affine; offsets below are compile-time)
    const int base_m0 = wbit * 33 + lane;                          // + h*66
    const int base_m1 = (wbit * 16 + ((lane >> 2) & 7) * 2) * 33 + (lane & 3);
    #define OFF1(h) (((h) >> 3) * 33 + ((h) & 7) * 4)

    float2 r[NREG];
    #pragma unroll
    for (int h = 0; h < NREG; ++h) r[h] = make_float2(0.f, 0.f);
    if (tb == 0) r[0].x = 1.f;                                     // |0...0>

    #pragma unroll 1
    for (int k = 0; k < NBLK; ++k) {
        #pragma unroll
        for (int sweep = 0; sweep < 2; ++sweep) {
            const float2* __restrict__ ry = gRy[k][sweep];
            // M0 reg wires 0..3 (h bit 3-wr)
            #pragma unroll
            for (int wr = 0; wr < 4; ++wr) {
                float2 rc = ry[wr];
                const int m = 1 << (3 - wr);
                #pragma unroll
                for (int h = 0; h < NREG; ++h)
                    if (!(h & m)) rotp(r[h], r[h | m], rc.x, rc.y);
            }
            // transpose M0 -> M1
            __syncthreads();
            #pragma unroll
            for (int h = 0; h < NREG; ++h)
                st[h * 66 + base_m0] = r[h];
            __syncthreads();
            #pragma unroll
            for (int h = 0; h < NREG; ++h)
                r[h] = st[base_m1 + OFF1(h)];
            // M1 reg wires 4..7 (h bit 7-wr)
            #pragma unroll
            for (int wr = 4; wr < 8; ++wr) {
                float2 rc = ry[wr];
                const int m = 1 << (7 - wr);
                #pragma unroll
                for (int h = 0; h < NREG; ++h)
                    if (!(h & m)) rotp(r[h], r[h | m], rc.x, rc.y);
            }
            // M1 lane wires 8 (l1, mask 2) and 9 (l0, mask 1) via shfl
            #pragma unroll
            for (int wr = 8; wr < 10; ++wr) {
                const int m = (wr == 8) ? 2 : 1;
                float2 rc = ry[wr];
                const float cc = rc.x;
                const float ss = (lane & m) ? rc.y : -rc.y;
                #pragma unroll
                for (int h = 0; h < NREG; ++h) {
                    float px = __shfl_xor_sync(0xffffffffu, r[h].x, m);
                    float py = __shfl_xor_sync(0xffffffffu, r[h].y, m);
                    r[h].x = fmaf(cc, r[h].x, ss * px);
                    r[h].y = fmaf(cc, r[h].y, ss * py);
                }
            }
            // write M1, gather by perm into M0 fused with diag B / C'
            __syncthreads();
            #pragma unroll
            for (int h = 0; h < NREG; ++h)
                st[base_m1 + OFF1(h)] = r[h];
            __syncthreads();
            const float2* __restrict__ T = sweep ? gC[k] : gB[k];
            #pragma unroll
            for (int h = 0; h < 8; ++h) {
                const int Kh = perm_of(h << 6);           // compile-time
                int hi = (Kh >> 5) ^ Pthi, lo = (Kh & 31) ^ Ptlo;
                float2 v = st[hi * 33 + lo];
                r[h] = cmul(v, __ldg(&T[(h << 6) | tb]));
            }
            __syncwarp();                                  // bound LDG front-batching
            #pragma unroll
            for (int h = 8; h < NREG; ++h) {
                const int Kh = perm_of(h << 6);           // compile-time
                int hi = (Kh >> 5) ^ Pthi, lo = (Kh & 31) ^ Ptlo;
                float2 v = st[hi * 33 + lo];
                r[h] = cmul(v, __ldg(&T[(h << 6) | tb]));
            }
        }
        // encoding between blocks (state in M0)
        if (k != NBLK - 1) {
            #pragma unroll
            for (int h = 0; h < NREG; ++h) {
                float ang = langle;
                #pragma unroll
                for (int wr = 0; wr < 4; ++wr)
                    ang += ((h >> (3 - wr)) & 1) ? -xv[wr] : xv[wr];
                float c, si;
                __sincosf(-0.5f * ang, &si, &c);
                r[h] = cmul(r[h], make_float2(c, si));
            }
        }
    }

    // expectation values: out[b][w] = sum_s |a_s|^2 * z[w][s]
    float acc[NW];
    #pragma unroll
    for (int w = 0; w < NW; ++w) acc[w] = 0.f;
    float totP = 0.f;
    #pragma unroll
    for (int h = 0; h < NREG; ++h) {
        float p = fmaf(r[h].x, r[h].x, r[h].y * r[h].y);
        totP += p;
        #pragma unroll
        for (int wr = 0; wr < 4; ++wr)
            acc[wr] += ((h >> (3 - wr)) & 1) ? -p : p;
    }
    #pragma unroll
    for (int w = 4; w < NW; ++w)
        acc[w] = ((tb >> (9 - w)) & 1) ? -totP : totP;

    #pragma unroll
    for (int off = 16; off; off >>= 1)
        #pragma unroll
        for (int w = 0; w < NW; ++w)
            acc[w] += __shfl_xor_sync(0xffffffffu, acc[w], off);

    if (lane == 0) {
        #pragma unroll
        for (int w = 0; w < NW; ++w) red[wbit][w] = acc[w];
    }
    __syncthreads();
    if (tid < NW) out[b * NW + tid] = red[0][tid] + red[1][tid];
}

extern "C" void kernel_launch(void* const* d_in, const int* in_sizes, int n_in,
                              void* d_out, int out_size) {
    const float* x      = (const float*)d_in[0];
    const float* params = (const float*)d_in[1];
    float* out = (float*)d_out;
    int bsz = in_sizes[0] / NW;           // 2048
    precompute_kernel<<<1, QDIM>>>(params);
    qsim_kernel<<<bsz, CTA>>>(x, out);
}

// round 12
// speedup vs baseline: 2.8688x; 1.0006x over previous
#include <cuda_runtime.h>

#define NW    10
#define QDIM  1024
#define NBLK  4
#define NREG  16                    // amplitudes per thread
#define CTA   64                    // 2 warps = one batch element

// Phase tables (params-only). A folded into previous C'; A[0] = global phase (dropped).
// B[k][s]  = exp(-i/2 * (p3.z[s] + p2.z[perm[s]]))
// C'[k][s] = exp(-i/2 * (p5.z[perm[s]] + pA(k+1).z[s]))
__device__ float2 gB[NBLK][QDIM];
__device__ float2 gC[NBLK][QDIM];
__device__ float2 gRy[NBLK][2][NW];   // (cos(th/2), sin(th/2))

// CX-ring permutation, closed form (GF(2)-linear).
__host__ __device__ __forceinline__ int perm_of(int s) {
    int lo = (s ^ (s >> 1)) & 0xFF;
    int b0 = s & 1, b8 = (s >> 8) & 1, b9 = (s >> 9) & 1;
    return lo | ((b8 ^ b9 ^ b0) << 8) | ((b9 ^ b0) << 9);
}

__device__ __forceinline__ float dotz(const float* __restrict__ p, int s) {
    float d = 0.f;
    #pragma unroll
    for (int w = 0; w < NW; ++w)
        d += ((s >> (9 - w)) & 1) ? -p[w] : p[w];
    return d;
}

__global__ __launch_bounds__(QDIM)
void precompute_kernel(const float* __restrict__ params) {
    int s = threadIdx.x;
    if (s < NBLK * 2 * NW) {
        int k = s / (2 * NW), r = s % (2 * NW);
        int sweep = r / NW, w = r % NW;
        float th = params[(k * 6 + (sweep ? 4 : 1)) * NW + w];
        gRy[k][sweep][w] = make_float2(cosf(0.5f * th), sinf(0.5f * th));
    }
    int ps = perm_of(s);
    #pragma unroll 1
    for (int k = 0; k < NBLK; ++k) {
        const float* p = params + k * 6 * NW;
        float aB = dotz(p + 3 * NW, s) + dotz(p + 2 * NW, ps);
        float aC = dotz(p + 5 * NW, ps);
        if (k < NBLK - 1)
            aC += dotz(params + ((k + 1) * 6 + 0) * NW, s);
        float c, si;
        sincosf(-0.5f * aB, &si, &c); gB[k][s] = make_float2(c, si);
        sincosf(-0.5f * aC, &si, &c); gC[k][s] = make_float2(c, si);
    }
}

__device__ __forceinline__ float2 cmul(float2 a, float2 b) {
    return make_float2(a.x * b.x - a.y * b.y, a.x * b.y + a.y * b.x);
}
__device__ __forceinline__ void rotp(float2& u, float2& v, float c, float s) {
    float2 nu = make_float2(fmaf(c, u.x, -s * v.x), fmaf(c, u.y, -s * v.y));
    float2 nv = make_float2(fmaf(s, u.x,  c * v.x), fmaf(s, u.y,  c * v.y));
    u = nu; v = nv;
}

// Padded-affine shared layout (float2 units): loc(s) = (s>>5)*33 + (s&31).
// All transpose addresses are base_thread + compile-time offset -> immediate LDS/STS.
//
// Layout M0 (canonical): s = (h<<6) | (wbit<<5) | lane
//   h bits -> wires 0..3 ; wbit -> wire 4 ; lane bits -> wires 5..9
// Layout M1: s = wbit<<9 | l4<<8 | l3<<7 | l2<<6 | (h<<2) | l1<<1 | l0
//   h bits -> wires 4..7 ; lane bits l1,l0 -> wires 8,9 (shfl) ;
//   wbit/l4/l3/l2 -> wires 0..3 (covered by M0)
__global__ __launch_bounds__(CTA)
void qsim_kernel(const float* __restrict__ x, float* __restrict__ out) {
    __shared__ float2 st[32 * 33];
    __shared__ float  red[2][NW];

    const int tid  = threadIdx.x;
    const int lane = tid & 31;
    const int wbit = tid >> 5;
    const int b    = blockIdx.x;
    const int tb   = (wbit << 5) | lane;          // low 6 bits of M0 state

    float xv[NW];
    #pragma unroll
    for (int w = 0; w < NW; ++w) xv[w] = __ldg(&x[b * NW + w]);

    // gather per-thread constants: g = Kh ^ Pt (GF2-linear perm)
    const int Pt   = perm_of(tb);
    const int Pthi = Pt >> 5, Ptlo = Pt & 31;

    // encoding angle part from thread bits (wires 4..9 <-> tb bits 5..0)
    float langle = 0.f;
    #pragma unroll
    for (int w = 4; w < NW; ++w)
        langle += ((tb >> (9 - w)) & 1) ? -xv[w] : xv[w];

    // transpose address bases (affine; offsets below are compile-time)
    const int base_m0 = wbit * 33 + lane;                          // + h*66
    const int base_m1 = (wbit * 16 + ((lane >> 2) & 7) * 2) * 33 + (lane & 3);
    #define OFF1(h) (((h) >> 3) * 33 + ((h) & 7) * 4)

    float2 r[NREG];
    #pragma unroll
    for (int h = 0; h < NREG; ++h) r[h] = make_float2(0.f, 0.f);
    if (tb == 0) r[0].x = 1.f;                                     // |0...0>

    #pragma unroll 1
    for (int k = 0; k < NBLK; ++k) {
        #pragma unroll
        for (int sweep = 0; sweep < 2; ++sweep) {
            const float2* __restrict__ ry = gRy[k][sweep];
            // M0 reg wires 0..3 (h bit 3-wr)
            #pragma unroll
            for (int wr = 0; wr < 4; ++wr) {
                float2 rc = ry[wr];
                const int m = 1 << (3 - wr);
                #pragma unroll
                for (int h = 0; h < NREG; ++h)
                    if (!(h & m)) rotp(r[h], r[h | m], rc.x, rc.y);
            }
            // transpose M0 -> M1
            __syncthreads();
            #pragma unroll
            for (int h = 0; h < NREG; ++h)
                st[h * 66 + base_m0] = r[h];
            __syncthreads();
            #pragma unroll
            for (int h = 0; h < NREG; ++h)
                r[h] = st[base_m1 + OFF1(h)];
            // M1 reg wires 4..7 (h bit 7-wr)
            #pragma unroll
            for (int wr = 4; wr < 8; ++wr) {
                float2 rc = ry[wr];
                const int m = 1 << (7 - wr);
                #pragma unroll
                for (int h = 0; h < NREG; ++h)
                    if (!(h & m)) rotp(r[h], r[h | m], rc.x, rc.y);
            }
            // M1 lane wires 8 (l1, mask 2) and 9 (l0, mask 1) via shfl
            #pragma unroll
            for (int wr = 8; wr < 10; ++wr) {
                const int m = (wr == 8) ? 2 : 1;
                float2 rc = ry[wr];
                const float cc = rc.x;
                const float ss = (lane & m) ? rc.y : -rc.y;
                #pragma unroll
                for (int h = 0; h < NREG; ++h) {
                    float px = __shfl_xor_sync(0xffffffffu, r[h].x, m);
                    float py = __shfl_xor_sync(0xffffffffu, r[h].y, m);
                    r[h].x = fmaf(cc, r[h].x, ss * px);
                    r[h].y = fmaf(cc, r[h].y, ss * py);
                }
            }
            // write M1, gather by perm into M0 fused with diag B / C'
            __syncthreads();
            #pragma unroll
            for (int h = 0; h < NREG; ++h)
                st[base_m1 + OFF1(h)] = r[h];
            __syncthreads();
            const float2* __restrict__ T = sweep ? gC[k] : gB[k];
            #pragma unroll
            for (int h = 0; h < 8; ++h) {
                const int Kh = perm_of(h << 6);           // compile-time
                int hi = (Kh >> 5) ^ Pthi, lo = (Kh & 31) ^ Ptlo;
                float2 v = st[hi * 33 + lo];
                r[h] = cmul(v, __ldg(&T[(h << 6) | tb]));
            }
            __syncwarp();                                  // bound LDG front-batching
            #pragma unroll
            for (int h = 8; h < NREG; ++h) {
                const int Kh = perm_of(h << 6);           // compile-time
                int hi = (Kh >> 5) ^ Pthi, lo = (Kh & 31) ^ Ptlo;
                float2 v = st[hi * 33 + lo];
                r[h] = cmul(v, __ldg(&T[(h << 6) | tb]));
            }
        }
        // encoding between blocks (state in M0)
        if (k != NBLK - 1) {
            #pragma unroll
            for (int h = 0; h < NREG; ++h) {
                float ang = langle;
                #pragma unroll
                for (int wr = 0; wr < 4; ++wr)
                    ang += ((h >> (3 - wr)) & 1) ? -xv[wr] : xv[wr];
                float c, si;
                __sincosf(-0.5f * ang, &si, &c);
                r[h] = cmul(r[h], make_float2(c, si));
            }
        }
    }

    // expectation values: out[b][w] = sum_s |a_s|^2 * z[w][s]
    float acc[NW];
    #pragma unroll
    for (int w = 0; w < NW; ++w) acc[w] = 0.f;
    float totP = 0.f;
    #pragma unroll
    for (int h = 0; h < NREG; ++h) {
        float p = fmaf(r[h].x, r[h].x, r[h].y * r[h].y);
        totP += p;
        #pragma unroll
        for (int wr = 0; wr < 4; ++wr)
            acc[wr] += ((h >> (3 - wr)) & 1) ? -p : p;
    }
    #pragma unroll
    for (int w = 4; w < NW; ++w)
        acc[w] = ((tb >> (9 - w)) & 1) ? -totP : totP;

    #pragma unroll
    for (int off = 16; off; off >>= 1)
        #pragma unroll
        for (int w = 0; w < NW; ++w)
            acc[w] += __shfl_xor_sync(0xffffffffu, acc[w], off);

    if (lane == 0) {
        #pragma unroll
        for (int w = 0; w < NW; ++w) red[wbit][w] = acc[w];
    }
    __syncthreads();
    if (tid < NW) out[b * NW + tid] = red[0][tid] + red[1][tid];
}

extern "C" void kernel_launch(void* const* d_in, const int* in_sizes, int n_in,
                              void* d_out, int out_size) {
    const float* x      = (const float*)d_in[0];
    const float* params = (const float*)d_in[1];
    float* out = (float*)d_out;
    int bsz = in_sizes[0] / NW;           // 2048
    precompute_kernel<<<1, QDIM>>>(params);
    qsim_kernel<<<bsz, CTA>>>(x, out);
}